// round 12
// baseline (speedup 1.0000x reference)
#include <cuda_runtime.h>
#include <cuda_fp16.h>
#include <cstdint>
#include <math.h>

#define BATCH   4
#define NTOK    2048
#define CDIM    768
#define HEADS   16
#define HD      48
#define MROWS   (BATCH*NTOK)          // 8192
#define SCALE   0.14433756729740643f  // 48^-0.5
#define LOG2E   1.4426950408889634f
#define QSC     (SCALE*LOG2E)

// ---------------- scratch (device globals; no allocation allowed) ----------
__device__ __align__(256) __half g_Xh[(size_t)MROWS*CDIM];
__device__ __align__(256) __half g_Wh[4][(size_t)CDIM*CDIM];   // q,k,v,o
__device__ __align__(256) __half g_Qh[(size_t)MROWS*CDIM];     // [B,H,N,D], Q pre-scaled by SCALE*log2e
__device__ __align__(256) __half g_Kh[(size_t)MROWS*CDIM];
__device__ __align__(256) __half g_Vh[(size_t)MROWS*CDIM];
__device__ __align__(256) float  g_Y [(size_t)MROWS*CDIM];     // y + x (fp32)
__device__ __align__(256) __half g_Yh[(size_t)MROWS*CDIM];     // fp16 y (GEMM input)

// ------------------------------ helpers ------------------------------------
__device__ __forceinline__ unsigned cvta_s(const void* p) {
    return (unsigned)__cvta_generic_to_shared(p);
}
__device__ __forceinline__ void ldsm_x4(unsigned& r0, unsigned& r1,
                                        unsigned& r2, unsigned& r3, unsigned a) {
    asm volatile("ldmatrix.sync.aligned.m8n8.x4.shared.b16 {%0,%1,%2,%3},[%4];"
                 : "=r"(r0), "=r"(r1), "=r"(r2), "=r"(r3) : "r"(a));
}
__device__ __forceinline__ void ldsm_x4_t(unsigned& r0, unsigned& r1,
                                          unsigned& r2, unsigned& r3, unsigned a) {
    asm volatile("ldmatrix.sync.aligned.m8n8.x4.trans.shared.b16 {%0,%1,%2,%3},[%4];"
                 : "=r"(r0), "=r"(r1), "=r"(r2), "=r"(r3) : "r"(a));
}
__device__ __forceinline__ void mma16816(float* c, unsigned a0, unsigned a1,
                                         unsigned a2, unsigned a3,
                                         unsigned b0, unsigned b1) {
    asm volatile("mma.sync.aligned.m16n8k16.row.col.f32.f16.f16.f32 "
                 "{%0,%1,%2,%3},{%4,%5,%6,%7},{%8,%9},{%0,%1,%2,%3};"
                 : "+f"(c[0]), "+f"(c[1]), "+f"(c[2]), "+f"(c[3])
                 : "r"(a0), "r"(a1), "r"(a2), "r"(a3), "r"(b0), "r"(b1));
}
__device__ __forceinline__ unsigned f2_to_h2(float a, float b) {
    __half2 h = __floats2half2_rn(a, b);
    return *reinterpret_cast<unsigned*>(&h);
}
__device__ __forceinline__ unsigned ex2h2(unsigned s) {
    unsigned d;
    asm("ex2.approx.f16x2 %0, %1;" : "=r"(d) : "r"(s));
    return d;
}
__device__ __forceinline__ unsigned hadd2u(unsigned a, unsigned b) {
    unsigned d;
    asm("add.f16x2 %0, %1, %2;" : "=r"(d) : "r"(a), "r"(b));
    return d;
}
__device__ __forceinline__ void cp_async16(unsigned saddr, const void* gaddr) {
    asm volatile("cp.async.cg.shared.global [%0], [%1], 16;"
                 :: "r"(saddr), "l"(gaddr) : "memory");
}
__device__ __forceinline__ void cp_commit() {
    asm volatile("cp.async.commit_group;" ::: "memory");
}
#define SW128(o) ((o) ^ (((o) >> 3) & 0x70))

// ---------------------------------------------------------------------------
// fused fp32 -> fp16 conversion (2 float4 per thread)
// ---------------------------------------------------------------------------
#define N4X (MROWS*CDIM/4)
#define N4W (CDIM*CDIM/4)
#define NCVT ((N4X + 4*N4W) / 2)

__global__ void cvt_all(const float* __restrict__ x,
                        const float* __restrict__ wq, const float* __restrict__ wk,
                        const float* __restrict__ wv, const float* __restrict__ wo)
{
    int t = blockIdx.x * 256 + threadIdx.x;
    if (t >= NCVT) return;
    #pragma unroll
    for (int rep = 0; rep < 2; rep++) {
        int i = t * 2 + rep;
        const float* src;
        __half2* dst;
        int off;
        if (i < N4X) {
            src = x; dst = (__half2*)g_Xh; off = i;
        } else {
            int j = i - N4X;
            int w = j / N4W;
            off = j - w * N4W;
            src = (w == 0) ? wq : (w == 1) ? wk : (w == 2) ? wv : wo;
            dst = (__half2*)g_Wh[w];
        }
        float4 v = ((const float4*)src)[off];
        dst[2*off]   = __floats2half2_rn(v.x, v.y);
        dst[2*off+1] = __floats2half2_rn(v.z, v.w);
    }
}

// ---------------------------------------------------------------------------
// HGEMM, 64x128 CTA tile, BK=64, 3-stage cp.async, SW128 rows, (256,3).
// ---------------------------------------------------------------------------
#define NIT   12              // 768 / 64
#define NSTG  3
#define STG_BYTES 24576
#define HGEMM_SMEM (NSTG*STG_BYTES)

__global__ __launch_bounds__(256, 3) void hgemm_kernel(
    const float* __restrict__ b0p, const float* __restrict__ b1p,
    const float* __restrict__ b2p, float* __restrict__ outp,
    int qkv)
{
    extern __shared__ __align__(1024) char smraw[];
    unsigned smb = cvta_s(smraw);

    int tid = threadIdx.x, lane = tid & 31, warp = tid >> 5;
    int m0 = blockIdx.y * 64, n0 = blockIdx.x * 128;
    int mode = qkv ? (int)blockIdx.z : 3;

    const __half* A = qkv ? g_Xh : g_Yh;
    const __half* W = g_Wh[mode];
    const float* bias = qkv ? (mode == 0 ? b0p : (mode == 1 ? b1p : b2p)) : b0p;

    int wm = (warp >> 2) * 32, wn = (warp & 3) * 32;
    int g = lane >> 3, L = lane & 7;

    float acc[2][4][4];
    #pragma unroll
    for (int i = 0; i < 2; i++)
        #pragma unroll
        for (int j = 0; j < 4; j++)
            #pragma unroll
            for (int e = 0; e < 4; e++) acc[i][j][e] = 0.f;

    auto load_tile = [&](int kt, int st) {
        #pragma unroll
        for (int p = 0; p < 6; p++) {
            int idx = tid + p * 256;            // 0..1535
            if (idx < 512) {
                int row = idx >> 3, c16 = idx & 7;
                unsigned off = SW128((unsigned)(row * 128 + c16 * 16));
                cp_async16(smb + st * STG_BYTES + off,
                           A + (size_t)(m0 + row) * CDIM + kt * 64 + c16 * 8);
            } else {
                int j = idx - 512;
                int row = j >> 3, c16 = j & 7;
                unsigned off = SW128((unsigned)(row * 128 + c16 * 16));
                cp_async16(smb + st * STG_BYTES + 8192 + off,
                           W + (size_t)(n0 + row) * CDIM + kt * 64 + c16 * 8);
            }
        }
        cp_commit();
    };

    load_tile(0, 0);
    load_tile(1, 1);

    for (int c = 0; c < NIT; c++) {
        if (c < NIT - 1) asm volatile("cp.async.wait_group 1;" ::: "memory");
        else             asm volatile("cp.async.wait_group 0;" ::: "memory");
        __syncthreads();
        if (c + 2 < NIT) load_tile(c + 2, (c + 2) % NSTG);

        unsigned ab = smb + (c % NSTG) * STG_BYTES;
        unsigned bb = ab + 8192;

        #pragma unroll
        for (int s = 0; s < 4; s++) {
            int kbA = s * 32 + ((lane >> 4) << 4);
            unsigned af[2][4];
            #pragma unroll
            for (int mt = 0; mt < 2; mt++) {
                unsigned row = wm + mt * 16 + (lane & 15);
                ldsm_x4(af[mt][0], af[mt][1], af[mt][2], af[mt][3],
                        ab + SW128(row * 128 + kbA));
            }
            unsigned bf[4][2];
            int kbB = s * 32 + ((g & 1) << 4);
            #pragma unroll
            for (int nt2 = 0; nt2 < 2; nt2++) {
                unsigned brow = wn + nt2 * 16 + ((g >> 1) << 3) + L;
                unsigned r0, r1, r2, r3;
                ldsm_x4(r0, r1, r2, r3, bb + SW128(brow * 128 + kbB));
                bf[nt2*2][0] = r0;   bf[nt2*2][1] = r1;
                bf[nt2*2+1][0] = r2; bf[nt2*2+1][1] = r3;
            }
            #pragma unroll
            for (int mt = 0; mt < 2; mt++)
                #pragma unroll
                for (int nt = 0; nt < 4; nt++)
                    mma16816(acc[mt][nt], af[mt][0], af[mt][1], af[mt][2],
                             af[mt][3], bf[nt][0], bf[nt][1]);
        }
    }

    // epilogue
    if (qkv) {
        __half* dst = (mode == 0) ? g_Qh : ((mode == 1) ? g_Kh : g_Vh);
        float sc = (mode == 0) ? QSC : 1.f;
        #pragma unroll
        for (int mt = 0; mt < 2; mt++) {
            #pragma unroll
            for (int nt = 0; nt < 4; nt++) {
                int mr = m0 + wm + mt*16 + (lane >> 2);
                int c  = n0 + wn + nt*8 + ((lane & 3) << 1);
                int hh = c / HD, d = c - hh*HD;
                int bb2 = mr >> 11, nn = mr & 2047;
                size_t base = (size_t)(bb2*HEADS + hh) * NTOK * HD + d;
                __half2 v0 = __floats2half2_rn((acc[mt][nt][0] + bias[c])*sc,
                                               (acc[mt][nt][1] + bias[c+1])*sc);
                __half2 v1 = __floats2half2_rn((acc[mt][nt][2] + bias[c])*sc,
                                               (acc[mt][nt][3] + bias[c+1])*sc);
                *(__half2*)&dst[base + (size_t)nn*HD]     = v0;
                *(__half2*)&dst[base + (size_t)(nn+8)*HD] = v1;
            }
        }
    } else {
        #pragma unroll
        for (int mt = 0; mt < 2; mt++) {
            #pragma unroll
            for (int nt = 0; nt < 4; nt++) {
                int mr = m0 + wm + mt*16 + (lane >> 2);
                int c  = n0 + wn + nt*8 + ((lane & 3) << 1);
                size_t i0 = (size_t)mr * CDIM + c;
                size_t i1 = (size_t)(mr + 8) * CDIM + c;
                outp[i0]   = acc[mt][nt][0] + bias[c]   + g_Y[i0];
                outp[i0+1] = acc[mt][nt][1] + bias[c+1] + g_Y[i0+1];
                outp[i1]   = acc[mt][nt][2] + bias[c]   + g_Y[i1];
                outp[i1+1] = acc[mt][nt][3] + bias[c+1] + g_Y[i1+1];
            }
        }
    }
}

// ---------------------------------------------------------------------------
// FlashAttention fp16, no online max, cp.async K/V pipeline.
// Q-tile 256 rows, 512 threads (16 warps x 16 rows) -> K/V L2 traffic halved.
// Q pre-scaled by SCALE*log2e; P = ex2(s).
// dyn smem: Qs 28672 + Ks 2x7168 + Vs 2x7168 = 57344 B.
// ---------------------------------------------------------------------------
#define FQS_OFF  0
#define FKS_OFF  28672
#define FVS_OFF  (28672 + 2*7168)
#define FKV_B    7168                 // 64 rows x 56 halfs x 2B
#define FATTN_SMEM (FVS_OFF + 2*7168)

__global__ __launch_bounds__(512) void fattn_kernel(const float* __restrict__ x)
{
    extern __shared__ __align__(256) char fsm[];
    __half* Qs = (__half*)(fsm + FQS_OFF);

    int tid = threadIdx.x, lane = tid & 31, w = tid >> 5;   // w: 0..15
    int bh = blockIdx.y, q0 = blockIdx.x * 256;
    int b = bh >> 4, hh = bh & 15;

    const __half* Qg = g_Qh + (size_t)bh * NTOK * HD;
    const __half* Kg = g_Kh + (size_t)bh * NTOK * HD;
    const __half* Vg = g_Vh + (size_t)bh * NTOK * HD;

    // one K/V tile = 64 rows x 48 halfs -> 384 chunks each (768 total)
    auto load_kv = [&](int kt, int bufi) {
        int k0 = kt * 64;
        #pragma unroll
        for (int i = 0; i < 2; i++) {
            int idx = tid + i * 512;          // 0..1023
            if (idx < 768) {
                int isv = idx >= 384;
                int c = idx - (isv ? 384 : 0);
                int r = c / 6, cc = c % 6;
                const __half* gp = (isv ? Vg : Kg) + (size_t)(k0 + r) * HD + cc * 8;
                unsigned sa = cvta_s(fsm + (isv ? FVS_OFF : FKS_OFF) + bufi * FKV_B
                                     + (r * 56 + cc * 8) * 2);
                cp_async16(sa, gp);
            }
        }
        cp_commit();
    };

    // load Q tile (256 x 48 halfs = 1536 chunks)
    for (int idx = tid; idx < 256*6; idx += 512) {
        int r = idx / 6, c = idx % 6;
        *(uint4*)&Qs[r*56 + c*8] =
            *(const uint4*)(Qg + (size_t)(q0 + r)*HD + c*8);
    }
    load_kv(0, 0);
    __syncthreads();

    unsigned qa[3][4];
    #pragma unroll
    for (int ks = 0; ks < 3; ks++)
        ldsm_x4(qa[ks][0], qa[ks][1], qa[ks][2], qa[ks][3],
                cvta_s(&Qs[(w*16 + (lane & 15))*56 + ks*16 + ((lane >> 4) << 3)]));

    float lr0 = 0.f, lr1 = 0.f;
    float oacc[6][4];
    #pragma unroll
    for (int i = 0; i < 6; i++)
        #pragma unroll
        for (int e = 0; e < 4; e++) oacc[i][e] = 0.f;

    int g = lane >> 3, L = lane & 7;
    const int NT = NTOK / 64;         // 32

    for (int kt = 0; kt < NT; kt++) {
        int cur = kt & 1;
        if (kt + 1 < NT) {
            load_kv(kt + 1, cur ^ 1);
            asm volatile("cp.async.wait_group 1;" ::: "memory");
        } else {
            asm volatile("cp.async.wait_group 0;" ::: "memory");
        }
        __syncthreads();

        const __half* Ksb = (const __half*)(fsm + FKS_OFF + cur * FKV_B);
        const __half* Vsb = (const __half*)(fsm + FVS_OFF + cur * FKV_B);

        float sacc[8][4];
        #pragma unroll
        for (int i = 0; i < 8; i++)
            #pragma unroll
            for (int e = 0; e < 4; e++) sacc[i][e] = 0.f;

        #pragma unroll
        for (int ks = 0; ks < 3; ks++) {
            #pragma unroll
            for (int nt2 = 0; nt2 < 4; nt2++) {
                int brow = nt2*16 + ((g >> 1) << 3) + L;
                int bcol = ks*16 + ((g & 1) << 3);
                unsigned r0, r1, r2, r3;
                ldsm_x4(r0, r1, r2, r3, cvta_s(&Ksb[brow*56 + bcol]));
                mma16816(sacc[nt2*2],   qa[ks][0], qa[ks][1], qa[ks][2], qa[ks][3], r0, r1);
                mma16816(sacc[nt2*2+1], qa[ks][0], qa[ks][1], qa[ks][2], qa[ks][3], r2, r3);
            }
        }

        unsigned P[4][4];
        #pragma unroll
        for (int j2 = 0; j2 < 4; j2++) {
            P[j2][0] = ex2h2(f2_to_h2(sacc[2*j2][0],   sacc[2*j2][1]));
            P[j2][1] = ex2h2(f2_to_h2(sacc[2*j2][2],   sacc[2*j2][3]));
            P[j2][2] = ex2h2(f2_to_h2(sacc[2*j2+1][0], sacc[2*j2+1][1]));
            P[j2][3] = ex2h2(f2_to_h2(sacc[2*j2+1][2], sacc[2*j2+1][3]));
        }

        {
            unsigned s0 = hadd2u(hadd2u(P[0][0], P[0][2]), hadd2u(P[1][0], P[1][2]));
            unsigned s1 = hadd2u(hadd2u(P[2][0], P[2][2]), hadd2u(P[3][0], P[3][2]));
            s0 = hadd2u(s0, s1);
            float2 f0 = __half22float2(*reinterpret_cast<__half2*>(&s0));
            lr0 += f0.x + f0.y;
            unsigned t0 = hadd2u(hadd2u(P[0][1], P[0][3]), hadd2u(P[1][1], P[1][3]));
            unsigned t1 = hadd2u(hadd2u(P[2][1], P[2][3]), hadd2u(P[3][1], P[3][3]));
            t0 = hadd2u(t0, t1);
            float2 f1 = __half22float2(*reinterpret_cast<__half2*>(&t0));
            lr1 += f1.x + f1.y;
        }

        #pragma unroll
        for (int j2 = 0; j2 < 4; j2++) {
            #pragma unroll
            for (int nt2 = 0; nt2 < 3; nt2++) {
                int vrow = j2*16 + ((g & 1) << 3) + L;
                int vcol = nt2*16 + ((g >> 1) << 3);
                unsigned r0, r1, r2, r3;
                ldsm_x4_t(r0, r1, r2, r3, cvta_s(&Vsb[vrow*56 + vcol]));
                mma16816(oacc[nt2*2],   P[j2][0], P[j2][1], P[j2][2], P[j2][3], r0, r1);
                mma16816(oacc[nt2*2+1], P[j2][0], P[j2][1], P[j2][2], P[j2][3], r2, r3);
            }
        }
        __syncthreads();
    }

    lr0 += __shfl_xor_sync(0xffffffffu, lr0, 1);
    lr0 += __shfl_xor_sync(0xffffffffu, lr0, 2);
    lr1 += __shfl_xor_sync(0xffffffffu, lr1, 1);
    lr1 += __shfl_xor_sync(0xffffffffu, lr1, 2);

    float inv0 = 1.f / lr0, inv1 = 1.f / lr1;
    int n_0 = q0 + w*16 + (lane >> 2);
    int n_1 = n_0 + 8;
    #pragma unroll
    for (int nt = 0; nt < 6; nt++) {
        int d = nt*8 + ((lane & 3) << 1);
        size_t i0 = ((size_t)(b*NTOK + n_0))*CDIM + hh*HD + d;
        size_t i1 = ((size_t)(b*NTOK + n_1))*CDIM + hh*HD + d;
        float x00 = x[i0],  x01 = x[i0+1], x10 = x[i1], x11 = x[i1+1];
        float y00 = oacc[nt][0]*inv0 + x00;
        float y01 = oacc[nt][1]*inv0 + x01;
        float y10 = oacc[nt][2]*inv1 + x10;
        float y11 = oacc[nt][3]*inv1 + x11;
        *(float2*)&g_Y[i0] = make_float2(y00 + x00, y01 + x01);
        *(float2*)&g_Y[i1] = make_float2(y10 + x10, y11 + x11);
        *(__half2*)&g_Yh[i0] = __floats2half2_rn(y00, y01);
        *(__half2*)&g_Yh[i1] = __floats2half2_rn(y10, y11);
    }
}

// ---------------------------------------------------------------------------
extern "C" void kernel_launch(void* const* d_in, const int* in_sizes, int n_in,
                              void* d_out, int out_size)
{
    const float* x  = (const float*)d_in[0];
    const float* wq = (const float*)d_in[1];
    const float* bq = (const float*)d_in[2];
    const float* wk = (const float*)d_in[3];
    const float* bk = (const float*)d_in[4];
    const float* wv = (const float*)d_in[5];
    const float* bv = (const float*)d_in[6];
    const float* wo = (const float*)d_in[7];
    const float* bo = (const float*)d_in[8];
    float* out = (float*)d_out;

    static int smem_set = 0;
    if (!smem_set) {
        cudaFuncSetAttribute(hgemm_kernel,
                             cudaFuncAttributeMaxDynamicSharedMemorySize,
                             HGEMM_SMEM);
        cudaFuncSetAttribute(fattn_kernel,
                             cudaFuncAttributeMaxDynamicSharedMemorySize,
                             FATTN_SMEM);
        smem_set = 1;
    }

    cvt_all<<<(NCVT + 255)/256, 256>>>(x, wq, wk, wv, wo);

    dim3 gq(CDIM/128, MROWS/64, 3);    // (6, 128, 3) fused Q,K,V
    hgemm_kernel<<<gq, 256, HGEMM_SMEM>>>(bq, bk, bv, out, 1);

    fattn_kernel<<<dim3(NTOK/256, BATCH*HEADS), 512, FATTN_SMEM>>>(x);

    dim3 go(CDIM/128, MROWS/64, 1);    // (6, 128)
    hgemm_kernel<<<go, 256, HGEMM_SMEM>>>(bo, bo, bo, out, 0);
}

// round 13
// speedup vs baseline: 1.1099x; 1.1099x over previous
#include <cuda_runtime.h>
#include <cuda_fp16.h>
#include <cstdint>
#include <math.h>

#define BATCH   4
#define NTOK    2048
#define CDIM    768
#define HEADS   16
#define HD      48
#define MROWS   (BATCH*NTOK)          // 8192
#define SCALE   0.14433756729740643f  // 48^-0.5
#define LOG2E   1.4426950408889634f
#define QSC     (SCALE*LOG2E)

// ---------------- scratch (device globals; no allocation allowed) ----------
__device__ __align__(256) __half g_Xh[(size_t)MROWS*CDIM];
__device__ __align__(256) __half g_Wh[4][(size_t)CDIM*CDIM];   // q,k,v,o
__device__ __align__(256) __half g_Qh[(size_t)MROWS*CDIM];     // [B,H,N,D], Q pre-scaled by SCALE*log2e
__device__ __align__(256) __half g_Kh[(size_t)MROWS*CDIM];
__device__ __align__(256) __half g_Vh[(size_t)MROWS*CDIM];
__device__ __align__(256) float  g_Y [(size_t)MROWS*CDIM];     // y + x (fp32)
__device__ __align__(256) __half g_Yh[(size_t)MROWS*CDIM];     // fp16 y (GEMM input)

// ------------------------------ helpers ------------------------------------
__device__ __forceinline__ unsigned cvta_s(const void* p) {
    return (unsigned)__cvta_generic_to_shared(p);
}
__device__ __forceinline__ void ldsm_x4(unsigned& r0, unsigned& r1,
                                        unsigned& r2, unsigned& r3, unsigned a) {
    asm volatile("ldmatrix.sync.aligned.m8n8.x4.shared.b16 {%0,%1,%2,%3},[%4];"
                 : "=r"(r0), "=r"(r1), "=r"(r2), "=r"(r3) : "r"(a));
}
__device__ __forceinline__ void ldsm_x4_t(unsigned& r0, unsigned& r1,
                                          unsigned& r2, unsigned& r3, unsigned a) {
    asm volatile("ldmatrix.sync.aligned.m8n8.x4.trans.shared.b16 {%0,%1,%2,%3},[%4];"
                 : "=r"(r0), "=r"(r1), "=r"(r2), "=r"(r3) : "r"(a));
}
__device__ __forceinline__ void mma16816(float* c, unsigned a0, unsigned a1,
                                         unsigned a2, unsigned a3,
                                         unsigned b0, unsigned b1) {
    asm volatile("mma.sync.aligned.m16n8k16.row.col.f32.f16.f16.f32 "
                 "{%0,%1,%2,%3},{%4,%5,%6,%7},{%8,%9},{%0,%1,%2,%3};"
                 : "+f"(c[0]), "+f"(c[1]), "+f"(c[2]), "+f"(c[3])
                 : "r"(a0), "r"(a1), "r"(a2), "r"(a3), "r"(b0), "r"(b1));
}
__device__ __forceinline__ unsigned f2_to_h2(float a, float b) {
    __half2 h = __floats2half2_rn(a, b);
    return *reinterpret_cast<unsigned*>(&h);
}
__device__ __forceinline__ unsigned ex2h2(unsigned s) {
    unsigned d;
    asm("ex2.approx.f16x2 %0, %1;" : "=r"(d) : "r"(s));
    return d;
}
__device__ __forceinline__ unsigned hadd2u(unsigned a, unsigned b) {
    unsigned d;
    asm("add.f16x2 %0, %1, %2;" : "=r"(d) : "r"(a), "r"(b));
    return d;
}
__device__ __forceinline__ void cp_async16(unsigned saddr, const void* gaddr) {
    asm volatile("cp.async.cg.shared.global [%0], [%1], 16;"
                 :: "r"(saddr), "l"(gaddr) : "memory");
}
__device__ __forceinline__ void cp_commit() {
    asm volatile("cp.async.commit_group;" ::: "memory");
}
#define SW128(o) ((o) ^ (((o) >> 3) & 0x70))

// ---------------------------------------------------------------------------
// fused fp32 -> fp16 conversion (2 float4 per thread)
// ---------------------------------------------------------------------------
#define N4X (MROWS*CDIM/4)
#define N4W (CDIM*CDIM/4)
#define NCVT ((N4X + 4*N4W) / 2)

__global__ void cvt_all(const float* __restrict__ x,
                        const float* __restrict__ wq, const float* __restrict__ wk,
                        const float* __restrict__ wv, const float* __restrict__ wo)
{
    int t = blockIdx.x * 256 + threadIdx.x;
    if (t >= NCVT) return;
    #pragma unroll
    for (int rep = 0; rep < 2; rep++) {
        int i = t * 2 + rep;
        const float* src;
        __half2* dst;
        int off;
        if (i < N4X) {
            src = x; dst = (__half2*)g_Xh; off = i;
        } else {
            int j = i - N4X;
            int w = j / N4W;
            off = j - w * N4W;
            src = (w == 0) ? wq : (w == 1) ? wk : (w == 2) ? wv : wo;
            dst = (__half2*)g_Wh[w];
        }
        float4 v = ((const float4*)src)[off];
        dst[2*off]   = __floats2half2_rn(v.x, v.y);
        dst[2*off+1] = __floats2half2_rn(v.z, v.w);
    }
}

// ---------------------------------------------------------------------------
// HGEMM-128: 128x128 CTA tile, BK=64, 3-stage cp.async, SW128, (256,2).
// For QKV (qkv path): mode = blockIdx.z -> scatter to g_Qh/g_Kh/g_Vh fp16.
// ---------------------------------------------------------------------------
#define NIT   12              // 768 / 64
#define G128_STG 32768
#define G128_SMEM (3*G128_STG)

__global__ __launch_bounds__(256, 2) void hgemm128_kernel(
    const float* __restrict__ b0p, const float* __restrict__ b1p,
    const float* __restrict__ b2p)
{
    extern __shared__ __align__(1024) char smraw[];
    unsigned smb = cvta_s(smraw);

    int tid = threadIdx.x, lane = tid & 31, warp = tid >> 5;
    int m0 = blockIdx.y * 128, n0 = blockIdx.x * 128;
    int mode = blockIdx.z;

    const __half* A = g_Xh;
    const __half* W = g_Wh[mode];
    const float* bias = (mode == 0) ? b0p : (mode == 1 ? b1p : b2p);

    int wm = (warp >> 2) * 64, wn = (warp & 3) * 32;
    int g = lane >> 3, L = lane & 7;

    float acc[4][4][4];
    #pragma unroll
    for (int i = 0; i < 4; i++)
        #pragma unroll
        for (int j = 0; j < 4; j++)
            #pragma unroll
            for (int e = 0; e < 4; e++) acc[i][j][e] = 0.f;

    auto load_tile = [&](int kt, int st) {
        #pragma unroll
        for (int p = 0; p < 4; p++) {
            int idx = tid + p * 256;            // 0..1023
            int row = idx >> 3, c16 = idx & 7;
            unsigned off = SW128((unsigned)(row * 128 + c16 * 16));
            cp_async16(smb + st * G128_STG + off,
                       A + (size_t)(m0 + row) * CDIM + kt * 64 + c16 * 8);
            cp_async16(smb + st * G128_STG + 16384 + off,
                       W + (size_t)(n0 + row) * CDIM + kt * 64 + c16 * 8);
        }
        cp_commit();
    };

    load_tile(0, 0);
    load_tile(1, 1);

    for (int c = 0; c < NIT; c++) {
        if (c < NIT - 1) asm volatile("cp.async.wait_group 1;" ::: "memory");
        else             asm volatile("cp.async.wait_group 0;" ::: "memory");
        __syncthreads();
        if (c + 2 < NIT) load_tile(c + 2, (c + 2) % 3);

        unsigned ab = smb + (c % 3) * G128_STG;
        unsigned bb = ab + 16384;

        #pragma unroll
        for (int s = 0; s < 4; s++) {
            int kbA = s * 32 + ((lane >> 4) << 4);
            unsigned af[4][4];
            #pragma unroll
            for (int mt = 0; mt < 4; mt++) {
                unsigned row = wm + mt * 16 + (lane & 15);
                ldsm_x4(af[mt][0], af[mt][1], af[mt][2], af[mt][3],
                        ab + SW128(row * 128 + kbA));
            }
            unsigned bf[4][2];
            int kbB = s * 32 + ((g & 1) << 4);
            #pragma unroll
            for (int nt2 = 0; nt2 < 2; nt2++) {
                unsigned brow = wn + nt2 * 16 + ((g >> 1) << 3) + L;
                unsigned r0, r1, r2, r3;
                ldsm_x4(r0, r1, r2, r3, bb + SW128(brow * 128 + kbB));
                bf[nt2*2][0] = r0;   bf[nt2*2][1] = r1;
                bf[nt2*2+1][0] = r2; bf[nt2*2+1][1] = r3;
            }
            #pragma unroll
            for (int mt = 0; mt < 4; mt++)
                #pragma unroll
                for (int nt = 0; nt < 4; nt++)
                    mma16816(acc[mt][nt], af[mt][0], af[mt][1], af[mt][2],
                             af[mt][3], bf[nt][0], bf[nt][1]);
        }
    }

    __half* dst = (mode == 0) ? g_Qh : ((mode == 1) ? g_Kh : g_Vh);
    float sc = (mode == 0) ? QSC : 1.f;
    #pragma unroll
    for (int mt = 0; mt < 4; mt++) {
        #pragma unroll
        for (int nt = 0; nt < 4; nt++) {
            int mr = m0 + wm + mt*16 + (lane >> 2);
            int c  = n0 + wn + nt*8 + ((lane & 3) << 1);
            int hh = c / HD, d = c - hh*HD;
            int bb2 = mr >> 11, nn = mr & 2047;
            size_t base = (size_t)(bb2*HEADS + hh) * NTOK * HD + d;
            __half2 v0 = __floats2half2_rn((acc[mt][nt][0] + bias[c])*sc,
                                           (acc[mt][nt][1] + bias[c+1])*sc);
            __half2 v1 = __floats2half2_rn((acc[mt][nt][2] + bias[c])*sc,
                                           (acc[mt][nt][3] + bias[c+1])*sc);
            *(__half2*)&dst[base + (size_t)nn*HD]     = v0;
            *(__half2*)&dst[base + (size_t)(nn+8)*HD] = v1;
        }
    }
}

// ---------------------------------------------------------------------------
// HGEMM-64: 64x128 CTA tile, BK=64, 3-stage cp.async, SW128, (256,3).
// O-projection: A=g_Yh, W=g_Wh[3]; out = acc + bias + g_Y  (g_Y = y+x).
// ---------------------------------------------------------------------------
#define G64_STG 24576
#define G64_SMEM (3*G64_STG)

__global__ __launch_bounds__(256, 3) void hgemm64_kernel(
    const float* __restrict__ bias, float* __restrict__ outp)
{
    extern __shared__ __align__(1024) char smraw[];
    unsigned smb = cvta_s(smraw);

    int tid = threadIdx.x, lane = tid & 31, warp = tid >> 5;
    int m0 = blockIdx.y * 64, n0 = blockIdx.x * 128;

    const __half* A = g_Yh;
    const __half* W = g_Wh[3];

    int wm = (warp >> 2) * 32, wn = (warp & 3) * 32;
    int g = lane >> 3, L = lane & 7;

    float acc[2][4][4];
    #pragma unroll
    for (int i = 0; i < 2; i++)
        #pragma unroll
        for (int j = 0; j < 4; j++)
            #pragma unroll
            for (int e = 0; e < 4; e++) acc[i][j][e] = 0.f;

    auto load_tile = [&](int kt, int st) {
        #pragma unroll
        for (int p = 0; p < 6; p++) {
            int idx = tid + p * 256;            // 0..1535
            if (idx < 512) {
                int row = idx >> 3, c16 = idx & 7;
                unsigned off = SW128((unsigned)(row * 128 + c16 * 16));
                cp_async16(smb + st * G64_STG + off,
                           A + (size_t)(m0 + row) * CDIM + kt * 64 + c16 * 8);
            } else {
                int j = idx - 512;
                int row = j >> 3, c16 = j & 7;
                unsigned off = SW128((unsigned)(row * 128 + c16 * 16));
                cp_async16(smb + st * G64_STG + 8192 + off,
                           W + (size_t)(n0 + row) * CDIM + kt * 64 + c16 * 8);
            }
        }
        cp_commit();
    };

    load_tile(0, 0);
    load_tile(1, 1);

    for (int c = 0; c < NIT; c++) {
        if (c < NIT - 1) asm volatile("cp.async.wait_group 1;" ::: "memory");
        else             asm volatile("cp.async.wait_group 0;" ::: "memory");
        __syncthreads();
        if (c + 2 < NIT) load_tile(c + 2, (c + 2) % 3);

        unsigned ab = smb + (c % 3) * G64_STG;
        unsigned bb = ab + 8192;

        #pragma unroll
        for (int s = 0; s < 4; s++) {
            int kbA = s * 32 + ((lane >> 4) << 4);
            unsigned af[2][4];
            #pragma unroll
            for (int mt = 0; mt < 2; mt++) {
                unsigned row = wm + mt * 16 + (lane & 15);
                ldsm_x4(af[mt][0], af[mt][1], af[mt][2], af[mt][3],
                        ab + SW128(row * 128 + kbA));
            }
            unsigned bf[4][2];
            int kbB = s * 32 + ((g & 1) << 4);
            #pragma unroll
            for (int nt2 = 0; nt2 < 2; nt2++) {
                unsigned brow = wn + nt2 * 16 + ((g >> 1) << 3) + L;
                unsigned r0, r1, r2, r3;
                ldsm_x4(r0, r1, r2, r3, bb + SW128(brow * 128 + kbB));
                bf[nt2*2][0] = r0;   bf[nt2*2][1] = r1;
                bf[nt2*2+1][0] = r2; bf[nt2*2+1][1] = r3;
            }
            #pragma unroll
            for (int mt = 0; mt < 2; mt++)
                #pragma unroll
                for (int nt = 0; nt < 4; nt++)
                    mma16816(acc[mt][nt], af[mt][0], af[mt][1], af[mt][2],
                             af[mt][3], bf[nt][0], bf[nt][1]);
        }
    }

    #pragma unroll
    for (int mt = 0; mt < 2; mt++) {
        #pragma unroll
        for (int nt = 0; nt < 4; nt++) {
            int mr = m0 + wm + mt*16 + (lane >> 2);
            int c  = n0 + wn + nt*8 + ((lane & 3) << 1);
            size_t i0 = (size_t)mr * CDIM + c;
            size_t i1 = (size_t)(mr + 8) * CDIM + c;
            outp[i0]   = acc[mt][nt][0] + bias[c]   + g_Y[i0];
            outp[i0+1] = acc[mt][nt][1] + bias[c+1] + g_Y[i0+1];
            outp[i1]   = acc[mt][nt][2] + bias[c]   + g_Y[i1];
            outp[i1+1] = acc[mt][nt][3] + bias[c+1] + g_Y[i1+1];
        }
    }
}

// ---------------------------------------------------------------------------
// FlashAttention fp16 (R9 base), no online max, 3-buffer K/V cp.async ring
// with a SINGLE __syncthreads per iteration (load target is 2 buffers ahead).
// Q pre-scaled by SCALE*log2e; P = ex2(s). Block = 128 q-rows, 8 warps.
// dyn smem: Qs 14336 + Ks 3x7168 + Vs 3x7168 = 57344 B.
// ---------------------------------------------------------------------------
#define FQS_OFF  0
#define FKS_OFF  14336
#define FVS_OFF  (14336 + 3*7168)
#define FKV_B    7168                 // 64 rows x 56 halfs x 2B
#define FATTN_SMEM (FVS_OFF + 3*7168)

__global__ __launch_bounds__(256) void fattn_kernel(const float* __restrict__ x)
{
    extern __shared__ __align__(256) char fsm[];
    __half* Qs = (__half*)(fsm + FQS_OFF);

    int tid = threadIdx.x, lane = tid & 31, w = tid >> 5;
    int bh = blockIdx.y, q0 = blockIdx.x * 128;
    int b = bh >> 4, hh = bh & 15;

    const __half* Qg = g_Qh + (size_t)bh * NTOK * HD;
    const __half* Kg = g_Kh + (size_t)bh * NTOK * HD;
    const __half* Vg = g_Vh + (size_t)bh * NTOK * HD;

    auto load_kv = [&](int kt, int bufi) {
        int k0 = kt * 64;
        #pragma unroll
        for (int i = 0; i < 3; i++) {
            int idx = tid + i * 256;
            int isv = idx >= 384;
            int c = isv ? idx - 384 : idx;
            int r = c / 6, cc = c % 6;
            const __half* gp = (isv ? Vg : Kg) + (size_t)(k0 + r) * HD + cc * 8;
            unsigned sa = cvta_s(fsm + (isv ? FVS_OFF : FKS_OFF) + bufi * FKV_B
                                 + (r * 56 + cc * 8) * 2);
            cp_async16(sa, gp);
        }
        cp_commit();
    };

    for (int idx = tid; idx < 128*6; idx += 256) {
        int r = idx / 6, c = idx % 6;
        *(uint4*)&Qs[r*56 + c*8] =
            *(const uint4*)(Qg + (size_t)(q0 + r)*HD + c*8);
    }
    load_kv(0, 0);
    load_kv(1, 1);
    __syncthreads();

    unsigned qa[3][4];
    #pragma unroll
    for (int ks = 0; ks < 3; ks++)
        ldsm_x4(qa[ks][0], qa[ks][1], qa[ks][2], qa[ks][3],
                cvta_s(&Qs[(w*16 + (lane & 15))*56 + ks*16 + ((lane >> 4) << 3)]));

    float lr0 = 0.f, lr1 = 0.f;
    float oacc[6][4];
    #pragma unroll
    for (int i = 0; i < 6; i++)
        #pragma unroll
        for (int e = 0; e < 4; e++) oacc[i][e] = 0.f;

    int g = lane >> 3, L = lane & 7;
    const int NT = NTOK / 64;         // 32

    for (int kt = 0; kt < NT; kt++) {
        if (kt < NT - 1) asm volatile("cp.async.wait_group 1;" ::: "memory");
        else             asm volatile("cp.async.wait_group 0;" ::: "memory");
        __syncthreads();
        if (kt + 2 < NT) load_kv(kt + 2, (kt + 2) % 3);

        const __half* Ksb = (const __half*)(fsm + FKS_OFF + (kt % 3) * FKV_B);
        const __half* Vsb = (const __half*)(fsm + FVS_OFF + (kt % 3) * FKV_B);

        float sacc[8][4];
        #pragma unroll
        for (int i = 0; i < 8; i++)
            #pragma unroll
            for (int e = 0; e < 4; e++) sacc[i][e] = 0.f;

        #pragma unroll
        for (int ks = 0; ks < 3; ks++) {
            #pragma unroll
            for (int nt2 = 0; nt2 < 4; nt2++) {
                int brow = nt2*16 + ((g >> 1) << 3) + L;
                int bcol = ks*16 + ((g & 1) << 3);
                unsigned r0, r1, r2, r3;
                ldsm_x4(r0, r1, r2, r3, cvta_s(&Ksb[brow*56 + bcol]));
                mma16816(sacc[nt2*2],   qa[ks][0], qa[ks][1], qa[ks][2], qa[ks][3], r0, r1);
                mma16816(sacc[nt2*2+1], qa[ks][0], qa[ks][1], qa[ks][2], qa[ks][3], r2, r3);
            }
        }

        unsigned P[4][4];
        #pragma unroll
        for (int j2 = 0; j2 < 4; j2++) {
            P[j2][0] = ex2h2(f2_to_h2(sacc[2*j2][0],   sacc[2*j2][1]));
            P[j2][1] = ex2h2(f2_to_h2(sacc[2*j2][2],   sacc[2*j2][3]));
            P[j2][2] = ex2h2(f2_to_h2(sacc[2*j2+1][0], sacc[2*j2+1][1]));
            P[j2][3] = ex2h2(f2_to_h2(sacc[2*j2+1][2], sacc[2*j2+1][3]));
        }

        {
            unsigned s0 = hadd2u(hadd2u(P[0][0], P[0][2]), hadd2u(P[1][0], P[1][2]));
            unsigned s1 = hadd2u(hadd2u(P[2][0], P[2][2]), hadd2u(P[3][0], P[3][2]));
            s0 = hadd2u(s0, s1);
            float2 f0 = __half22float2(*reinterpret_cast<__half2*>(&s0));
            lr0 += f0.x + f0.y;
            unsigned t0 = hadd2u(hadd2u(P[0][1], P[0][3]), hadd2u(P[1][1], P[1][3]));
            unsigned t1 = hadd2u(hadd2u(P[2][1], P[2][3]), hadd2u(P[3][1], P[3][3]));
            t0 = hadd2u(t0, t1);
            float2 f1 = __half22float2(*reinterpret_cast<__half2*>(&t0));
            lr1 += f1.x + f1.y;
        }

        #pragma unroll
        for (int j2 = 0; j2 < 4; j2++) {
            #pragma unroll
            for (int nt2 = 0; nt2 < 3; nt2++) {
                int vrow = j2*16 + ((g & 1) << 3) + L;
                int vcol = nt2*16 + ((g >> 1) << 3);
                unsigned r0, r1, r2, r3;
                ldsm_x4_t(r0, r1, r2, r3, cvta_s(&Vsb[vrow*56 + vcol]));
                mma16816(oacc[nt2*2],   P[j2][0], P[j2][1], P[j2][2], P[j2][3], r0, r1);
                mma16816(oacc[nt2*2+1], P[j2][0], P[j2][1], P[j2][2], P[j2][3], r2, r3);
            }
        }
    }

    lr0 += __shfl_xor_sync(0xffffffffu, lr0, 1);
    lr0 += __shfl_xor_sync(0xffffffffu, lr0, 2);
    lr1 += __shfl_xor_sync(0xffffffffu, lr1, 1);
    lr1 += __shfl_xor_sync(0xffffffffu, lr1, 2);

    float inv0 = 1.f / lr0, inv1 = 1.f / lr1;
    int n_0 = q0 + w*16 + (lane >> 2);
    int n_1 = n_0 + 8;
    #pragma unroll
    for (int nt = 0; nt < 6; nt++) {
        int d = nt*8 + ((lane & 3) << 1);
        size_t i0 = ((size_t)(b*NTOK + n_0))*CDIM + hh*HD + d;
        size_t i1 = ((size_t)(b*NTOK + n_1))*CDIM + hh*HD + d;
        float x00 = x[i0],  x01 = x[i0+1], x10 = x[i1], x11 = x[i1+1];
        float y00 = oacc[nt][0]*inv0 + x00;
        float y01 = oacc[nt][1]*inv0 + x01;
        float y10 = oacc[nt][2]*inv1 + x10;
        float y11 = oacc[nt][3]*inv1 + x11;
        *(float2*)&g_Y[i0] = make_float2(y00 + x00, y01 + x01);
        *(float2*)&g_Y[i1] = make_float2(y10 + x10, y11 + x11);
        *(__half2*)&g_Yh[i0] = __floats2half2_rn(y00, y01);
        *(__half2*)&g_Yh[i1] = __floats2half2_rn(y10, y11);
    }
}

// ---------------------------------------------------------------------------
extern "C" void kernel_launch(void* const* d_in, const int* in_sizes, int n_in,
                              void* d_out, int out_size)
{
    const float* x  = (const float*)d_in[0];
    const float* wq = (const float*)d_in[1];
    const float* bq = (const float*)d_in[2];
    const float* wk = (const float*)d_in[3];
    const float* bk = (const float*)d_in[4];
    const float* wv = (const float*)d_in[5];
    const float* bv = (const float*)d_in[6];
    const float* wo = (const float*)d_in[7];
    const float* bo = (const float*)d_in[8];
    float* out = (float*)d_out;

    static int smem_set = 0;
    if (!smem_set) {
        cudaFuncSetAttribute(hgemm128_kernel,
                             cudaFuncAttributeMaxDynamicSharedMemorySize, G128_SMEM);
        cudaFuncSetAttribute(hgemm64_kernel,
                             cudaFuncAttributeMaxDynamicSharedMemorySize, G64_SMEM);
        cudaFuncSetAttribute(fattn_kernel,
                             cudaFuncAttributeMaxDynamicSharedMemorySize, FATTN_SMEM);
        smem_set = 1;
    }

    cvt_all<<<(NCVT + 255)/256, 256>>>(x, wq, wk, wv, wo);

    dim3 gq(CDIM/128, MROWS/128, 3);   // (6, 64, 3) fused Q,K,V, 128-row tiles
    hgemm128_kernel<<<gq, 256, G128_SMEM>>>(bq, bk, bv);

    fattn_kernel<<<dim3(NTOK/128, BATCH*HEADS), 256, FATTN_SMEM>>>(x);

    dim3 go(CDIM/128, MROWS/64);       // (6, 128) O-proj, 64-row tiles
    hgemm64_kernel<<<go, 256, G64_SMEM>>>(bo, out);
}

// round 15
// speedup vs baseline: 1.1362x; 1.0237x over previous
#include <cuda_runtime.h>
#include <cuda_fp16.h>
#include <cstdint>
#include <math.h>

#define BATCH   4
#define NTOK    2048
#define CDIM    768
#define HEADS   16
#define HD      48
#define MROWS   (BATCH*NTOK)          // 8192
#define SCALE   0.14433756729740643f  // 48^-0.5
#define LOG2E   1.4426950408889634f
#define QSC     (SCALE*LOG2E)

// ---------------- scratch (device globals; no allocation allowed) ----------
__device__ __align__(256) __half g_Xh[(size_t)MROWS*CDIM];
__device__ __align__(256) __half g_Wh[4][(size_t)CDIM*CDIM];   // q,k,v,o
__device__ __align__(256) __half g_Qh[(size_t)MROWS*CDIM];     // [B,H,N,D], Q pre-scaled by SCALE*log2e
__device__ __align__(256) __half g_Kh[(size_t)MROWS*CDIM];
__device__ __align__(256) __half g_Vh[(size_t)MROWS*CDIM];
__device__ __align__(256) float  g_Y [(size_t)MROWS*CDIM];     // y + x (fp32)
__device__ __align__(256) __half g_Yh[(size_t)MROWS*CDIM];     // fp16 y (GEMM input)

// ------------------------------ helpers ------------------------------------
__device__ __forceinline__ unsigned cvta_s(const void* p) {
    return (unsigned)__cvta_generic_to_shared(p);
}
__device__ __forceinline__ void ldsm_x4(unsigned& r0, unsigned& r1,
                                        unsigned& r2, unsigned& r3, unsigned a) {
    asm volatile("ldmatrix.sync.aligned.m8n8.x4.shared.b16 {%0,%1,%2,%3},[%4];"
                 : "=r"(r0), "=r"(r1), "=r"(r2), "=r"(r3) : "r"(a));
}
__device__ __forceinline__ void ldsm_x4_t(unsigned& r0, unsigned& r1,
                                          unsigned& r2, unsigned& r3, unsigned a) {
    asm volatile("ldmatrix.sync.aligned.m8n8.x4.trans.shared.b16 {%0,%1,%2,%3},[%4];"
                 : "=r"(r0), "=r"(r1), "=r"(r2), "=r"(r3) : "r"(a));
}
__device__ __forceinline__ void mma16816(float* c, unsigned a0, unsigned a1,
                                         unsigned a2, unsigned a3,
                                         unsigned b0, unsigned b1) {
    asm volatile("mma.sync.aligned.m16n8k16.row.col.f32.f16.f16.f32 "
                 "{%0,%1,%2,%3},{%4,%5,%6,%7},{%8,%9},{%0,%1,%2,%3};"
                 : "+f"(c[0]), "+f"(c[1]), "+f"(c[2]), "+f"(c[3])
                 : "r"(a0), "r"(a1), "r"(a2), "r"(a3), "r"(b0), "r"(b1));
}
__device__ __forceinline__ unsigned f2_to_h2(float a, float b) {
    __half2 h = __floats2half2_rn(a, b);
    return *reinterpret_cast<unsigned*>(&h);
}
__device__ __forceinline__ unsigned ex2h2(unsigned s) {
    unsigned d;
    asm("ex2.approx.f16x2 %0, %1;" : "=r"(d) : "r"(s));
    return d;
}
__device__ __forceinline__ unsigned hadd2u(unsigned a, unsigned b) {
    unsigned d;
    asm("add.f16x2 %0, %1, %2;" : "=r"(d) : "r"(a), "r"(b));
    return d;
}
__device__ __forceinline__ void cp_async16(unsigned saddr, const void* gaddr) {
    asm volatile("cp.async.cg.shared.global [%0], [%1], 16;"
                 :: "r"(saddr), "l"(gaddr) : "memory");
}
__device__ __forceinline__ void cp_commit() {
    asm volatile("cp.async.commit_group;" ::: "memory");
}
#define SW128(o) ((o) ^ (((o) >> 3) & 0x70))

// ---------------------------------------------------------------------------
// fused fp32 -> fp16 conversion (2 float4 per thread)
// ---------------------------------------------------------------------------
#define N4X (MROWS*CDIM/4)
#define N4W (CDIM*CDIM/4)
#define NCVT ((N4X + 4*N4W) / 2)

__global__ void cvt_all(const float* __restrict__ x,
                        const float* __restrict__ wq, const float* __restrict__ wk,
                        const float* __restrict__ wv, const float* __restrict__ wo)
{
    int t = blockIdx.x * 256 + threadIdx.x;
    if (t >= NCVT) return;
    #pragma unroll
    for (int rep = 0; rep < 2; rep++) {
        int i = t * 2 + rep;
        const float* src;
        __half2* dst;
        int off;
        if (i < N4X) {
            src = x; dst = (__half2*)g_Xh; off = i;
        } else {
            int j = i - N4X;
            int w = j / N4W;
            off = j - w * N4W;
            src = (w == 0) ? wq : (w == 1) ? wk : (w == 2) ? wv : wo;
            dst = (__half2*)g_Wh[w];
        }
        float4 v = ((const float4*)src)[off];
        dst[2*off]   = __floats2half2_rn(v.x, v.y);
        dst[2*off+1] = __floats2half2_rn(v.z, v.w);
    }
}

// ---------------------------------------------------------------------------
// HGEMM-128: 128x128 CTA tile, BK=64, 3-stage cp.async, SW128, (256,2).
// QKV: mode = blockIdx.z -> scatter to g_Qh/g_Kh/g_Vh fp16 (Q scaled QSC).
// ---------------------------------------------------------------------------
#define NIT   12              // 768 / 64
#define G128_STG 32768
#define G128_SMEM (3*G128_STG)

__global__ __launch_bounds__(256, 2) void hgemm128_kernel(
    const float* __restrict__ b0p, const float* __restrict__ b1p,
    const float* __restrict__ b2p)
{
    cudaGridDependencySynchronize();   // PDL: wait for cvt_all's writes

    extern __shared__ __align__(1024) char smraw[];
    unsigned smb = cvta_s(smraw);

    int tid = threadIdx.x, lane = tid & 31, warp = tid >> 5;
    int m0 = blockIdx.y * 128, n0 = blockIdx.x * 128;
    int mode = blockIdx.z;

    const __half* A = g_Xh;
    const __half* W = g_Wh[mode];
    const float* bias = (mode == 0) ? b0p : (mode == 1 ? b1p : b2p);

    int wm = (warp >> 2) * 64, wn = (warp & 3) * 32;
    int g = lane >> 3, L = lane & 7;

    float acc[4][4][4];
    #pragma unroll
    for (int i = 0; i < 4; i++)
        #pragma unroll
        for (int j = 0; j < 4; j++)
            #pragma unroll
            for (int e = 0; e < 4; e++) acc[i][j][e] = 0.f;

    auto load_tile = [&](int kt, int st) {
        #pragma unroll
        for (int p = 0; p < 4; p++) {
            int idx = tid + p * 256;            // 0..1023
            int row = idx >> 3, c16 = idx & 7;
            unsigned off = SW128((unsigned)(row * 128 + c16 * 16));
            cp_async16(smb + st * G128_STG + off,
                       A + (size_t)(m0 + row) * CDIM + kt * 64 + c16 * 8);
            cp_async16(smb + st * G128_STG + 16384 + off,
                       W + (size_t)(n0 + row) * CDIM + kt * 64 + c16 * 8);
        }
        cp_commit();
    };

    load_tile(0, 0);
    load_tile(1, 1);

    for (int c = 0; c < NIT; c++) {
        if (c < NIT - 1) asm volatile("cp.async.wait_group 1;" ::: "memory");
        else             asm volatile("cp.async.wait_group 0;" ::: "memory");
        __syncthreads();
        if (c + 2 < NIT) load_tile(c + 2, (c + 2) % 3);

        unsigned ab = smb + (c % 3) * G128_STG;
        unsigned bb = ab + 16384;

        #pragma unroll
        for (int s = 0; s < 4; s++) {
            int kbA = s * 32 + ((lane >> 4) << 4);
            unsigned af[4][4];
            #pragma unroll
            for (int mt = 0; mt < 4; mt++) {
                unsigned row = wm + mt * 16 + (lane & 15);
                ldsm_x4(af[mt][0], af[mt][1], af[mt][2], af[mt][3],
                        ab + SW128(row * 128 + kbA));
            }
            unsigned bf[4][2];
            int kbB = s * 32 + ((g & 1) << 4);
            #pragma unroll
            for (int nt2 = 0; nt2 < 2; nt2++) {
                unsigned brow = wn + nt2 * 16 + ((g >> 1) << 3) + L;
                unsigned r0, r1, r2, r3;
                ldsm_x4(r0, r1, r2, r3, bb + SW128(brow * 128 + kbB));
                bf[nt2*2][0] = r0;   bf[nt2*2][1] = r1;
                bf[nt2*2+1][0] = r2; bf[nt2*2+1][1] = r3;
            }
            #pragma unroll
            for (int mt = 0; mt < 4; mt++)
                #pragma unroll
                for (int nt = 0; nt < 4; nt++)
                    mma16816(acc[mt][nt], af[mt][0], af[mt][1], af[mt][2],
                             af[mt][3], bf[nt][0], bf[nt][1]);
        }
    }

    __half* dst = (mode == 0) ? g_Qh : ((mode == 1) ? g_Kh : g_Vh);
    float sc = (mode == 0) ? QSC : 1.f;
    #pragma unroll
    for (int mt = 0; mt < 4; mt++) {
        #pragma unroll
        for (int nt = 0; nt < 4; nt++) {
            int mr = m0 + wm + mt*16 + (lane >> 2);
            int c  = n0 + wn + nt*8 + ((lane & 3) << 1);
            int hh = c / HD, d = c - hh*HD;
            int bb2 = mr >> 11, nn = mr & 2047;
            size_t base = (size_t)(bb2*HEADS + hh) * NTOK * HD + d;
            __half2 v0 = __floats2half2_rn((acc[mt][nt][0] + bias[c])*sc,
                                           (acc[mt][nt][1] + bias[c+1])*sc);
            __half2 v1 = __floats2half2_rn((acc[mt][nt][2] + bias[c])*sc,
                                           (acc[mt][nt][3] + bias[c+1])*sc);
            *(__half2*)&dst[base + (size_t)nn*HD]     = v0;
            *(__half2*)&dst[base + (size_t)(nn+8)*HD] = v1;
        }
    }
}

// ---------------------------------------------------------------------------
// HGEMM-64: 64x128 CTA tile, BK=64, 3-stage cp.async, SW128, (256,3).
// O-projection: A=g_Yh, W=g_Wh[3]; out = acc + bias + g_Y  (g_Y = y+x).
// ---------------------------------------------------------------------------
#define G64_STG 24576
#define G64_SMEM (3*G64_STG)

__global__ __launch_bounds__(256, 3) void hgemm64_kernel(
    const float* __restrict__ bias, float* __restrict__ outp)
{
    cudaGridDependencySynchronize();   // PDL: wait for fattn's writes

    extern __shared__ __align__(1024) char smraw[];
    unsigned smb = cvta_s(smraw);

    int tid = threadIdx.x, lane = tid & 31, warp = tid >> 5;
    int m0 = blockIdx.y * 64, n0 = blockIdx.x * 128;

    const __half* A = g_Yh;
    const __half* W = g_Wh[3];

    int wm = (warp >> 2) * 32, wn = (warp & 3) * 32;
    int g = lane >> 3, L = lane & 7;

    float acc[2][4][4];
    #pragma unroll
    for (int i = 0; i < 2; i++)
        #pragma unroll
        for (int j = 0; j < 4; j++)
            #pragma unroll
            for (int e = 0; e < 4; e++) acc[i][j][e] = 0.f;

    auto load_tile = [&](int kt, int st) {
        #pragma unroll
        for (int p = 0; p < 6; p++) {
            int idx = tid + p * 256;            // 0..1535
            if (idx < 512) {
                int row = idx >> 3, c16 = idx & 7;
                unsigned off = SW128((unsigned)(row * 128 + c16 * 16));
                cp_async16(smb + st * G64_STG + off,
                           A + (size_t)(m0 + row) * CDIM + kt * 64 + c16 * 8);
            } else {
                int j = idx - 512;
                int row = j >> 3, c16 = j & 7;
                unsigned off = SW128((unsigned)(row * 128 + c16 * 16));
                cp_async16(smb + st * G64_STG + 8192 + off,
                           W + (size_t)(n0 + row) * CDIM + kt * 64 + c16 * 8);
            }
        }
        cp_commit();
    };

    load_tile(0, 0);
    load_tile(1, 1);

    for (int c = 0; c < NIT; c++) {
        if (c < NIT - 1) asm volatile("cp.async.wait_group 1;" ::: "memory");
        else             asm volatile("cp.async.wait_group 0;" ::: "memory");
        __syncthreads();
        if (c + 2 < NIT) load_tile(c + 2, (c + 2) % 3);

        unsigned ab = smb + (c % 3) * G64_STG;
        unsigned bb = ab + 8192;

        #pragma unroll
        for (int s = 0; s < 4; s++) {
            int kbA = s * 32 + ((lane >> 4) << 4);
            unsigned af[2][4];
            #pragma unroll
            for (int mt = 0; mt < 2; mt++) {
                unsigned row = wm + mt * 16 + (lane & 15);
                ldsm_x4(af[mt][0], af[mt][1], af[mt][2], af[mt][3],
                        ab + SW128(row * 128 + kbA));
            }
            unsigned bf[4][2];
            int kbB = s * 32 + ((g & 1) << 4);
            #pragma unroll
            for (int nt2 = 0; nt2 < 2; nt2++) {
                unsigned brow = wn + nt2 * 16 + ((g >> 1) << 3) + L;
                unsigned r0, r1, r2, r3;
                ldsm_x4(r0, r1, r2, r3, bb + SW128(brow * 128 + kbB));
                bf[nt2*2][0] = r0;   bf[nt2*2][1] = r1;
                bf[nt2*2+1][0] = r2; bf[nt2*2+1][1] = r3;
            }
            #pragma unroll
            for (int mt = 0; mt < 2; mt++)
                #pragma unroll
                for (int nt = 0; nt < 4; nt++)
                    mma16816(acc[mt][nt], af[mt][0], af[mt][1], af[mt][2],
                             af[mt][3], bf[nt][0], bf[nt][1]);
        }
    }

    #pragma unroll
    for (int mt = 0; mt < 2; mt++) {
        #pragma unroll
        for (int nt = 0; nt < 4; nt++) {
            int mr = m0 + wm + mt*16 + (lane >> 2);
            int c  = n0 + wn + nt*8 + ((lane & 3) << 1);
            size_t i0 = (size_t)mr * CDIM + c;
            size_t i1 = (size_t)(mr + 8) * CDIM + c;
            outp[i0]   = acc[mt][nt][0] + bias[c]   + g_Y[i0];
            outp[i0+1] = acc[mt][nt][1] + bias[c+1] + g_Y[i0+1];
            outp[i1]   = acc[mt][nt][2] + bias[c]   + g_Y[i1];
            outp[i1+1] = acc[mt][nt][3] + bias[c+1] + g_Y[i1+1];
        }
    }
}

// ---------------------------------------------------------------------------
// FlashAttention fp16 (R9 exact), no online max, cp.async K/V double-buffer.
// Q pre-scaled by SCALE*log2e; P = ex2(s). Block = 128 q-rows, 8 warps.
// Writes g_Yh = y (fp16 GEMM input) and g_Y = y + x (fp32).
// ---------------------------------------------------------------------------
__global__ __launch_bounds__(256) void fattn_kernel(const float* __restrict__ x)
{
    cudaGridDependencySynchronize();   // PDL: wait for QKV writes

    __shared__ __half Qs[128*56];
    __shared__ __half Ks[2][64*56];
    __shared__ __half Vs[2][64*56];

    int tid = threadIdx.x, lane = tid & 31, w = tid >> 5;
    int bh = blockIdx.y, q0 = blockIdx.x * 128;
    int b = bh >> 4, hh = bh & 15;

    const __half* Qg = g_Qh + (size_t)bh * NTOK * HD;
    const __half* Kg = g_Kh + (size_t)bh * NTOK * HD;
    const __half* Vg = g_Vh + (size_t)bh * NTOK * HD;

    auto load_kv = [&](int kt, int bufi) {
        int k0 = kt * 64;
        #pragma unroll
        for (int i = 0; i < 3; i++) {
            int idx = tid + i * 256;
            int isv = idx >= 384;
            int c = isv ? idx - 384 : idx;
            int r = c / 6, cc = c % 6;
            const __half* gp = (isv ? Vg : Kg) + (size_t)(k0 + r) * HD + cc * 8;
            unsigned sa = cvta_s(&(isv ? Vs : Ks)[bufi][r * 56 + cc * 8]);
            cp_async16(sa, gp);
        }
        cp_commit();
    };

    for (int idx = tid; idx < 128*6; idx += 256) {
        int r = idx / 6, c = idx % 6;
        *(uint4*)&Qs[r*56 + c*8] =
            *(const uint4*)(Qg + (size_t)(q0 + r)*HD + c*8);
    }
    load_kv(0, 0);
    __syncthreads();

    unsigned qa[3][4];
    #pragma unroll
    for (int ks = 0; ks < 3; ks++)
        ldsm_x4(qa[ks][0], qa[ks][1], qa[ks][2], qa[ks][3],
                cvta_s(&Qs[(w*16 + (lane & 15))*56 + ks*16 + ((lane >> 4) << 3)]));

    float lr0 = 0.f, lr1 = 0.f;
    float oacc[6][4];
    #pragma unroll
    for (int i = 0; i < 6; i++)
        #pragma unroll
        for (int e = 0; e < 4; e++) oacc[i][e] = 0.f;

    int g = lane >> 3, L = lane & 7;
    const int NT = NTOK / 64;

    for (int kt = 0; kt < NT; kt++) {
        int cur = kt & 1;
        if (kt + 1 < NT) {
            load_kv(kt + 1, cur ^ 1);
            asm volatile("cp.async.wait_group 1;" ::: "memory");
        } else {
            asm volatile("cp.async.wait_group 0;" ::: "memory");
        }
        __syncthreads();

        float sacc[8][4];
        #pragma unroll
        for (int i = 0; i < 8; i++)
            #pragma unroll
            for (int e = 0; e < 4; e++) sacc[i][e] = 0.f;

        #pragma unroll
        for (int ks = 0; ks < 3; ks++) {
            #pragma unroll
            for (int nt2 = 0; nt2 < 4; nt2++) {
                int brow = nt2*16 + ((g >> 1) << 3) + L;
                int bcol = ks*16 + ((g & 1) << 3);
                unsigned r0, r1, r2, r3;
                ldsm_x4(r0, r1, r2, r3, cvta_s(&Ks[cur][brow*56 + bcol]));
                mma16816(sacc[nt2*2],   qa[ks][0], qa[ks][1], qa[ks][2], qa[ks][3], r0, r1);
                mma16816(sacc[nt2*2+1], qa[ks][0], qa[ks][1], qa[ks][2], qa[ks][3], r2, r3);
            }
        }

        unsigned P[4][4];
        #pragma unroll
        for (int j2 = 0; j2 < 4; j2++) {
            P[j2][0] = ex2h2(f2_to_h2(sacc[2*j2][0],   sacc[2*j2][1]));
            P[j2][1] = ex2h2(f2_to_h2(sacc[2*j2][2],   sacc[2*j2][3]));
            P[j2][2] = ex2h2(f2_to_h2(sacc[2*j2+1][0], sacc[2*j2+1][1]));
            P[j2][3] = ex2h2(f2_to_h2(sacc[2*j2+1][2], sacc[2*j2+1][3]));
        }

        {
            unsigned s0 = hadd2u(hadd2u(P[0][0], P[0][2]), hadd2u(P[1][0], P[1][2]));
            unsigned s1 = hadd2u(hadd2u(P[2][0], P[2][2]), hadd2u(P[3][0], P[3][2]));
            s0 = hadd2u(s0, s1);
            float2 f0 = __half22float2(*reinterpret_cast<__half2*>(&s0));
            lr0 += f0.x + f0.y;
            unsigned t0 = hadd2u(hadd2u(P[0][1], P[0][3]), hadd2u(P[1][1], P[1][3]));
            unsigned t1 = hadd2u(hadd2u(P[2][1], P[2][3]), hadd2u(P[3][1], P[3][3]));
            t0 = hadd2u(t0, t1);
            float2 f1 = __half22float2(*reinterpret_cast<__half2*>(&t0));
            lr1 += f1.x + f1.y;
        }

        #pragma unroll
        for (int j2 = 0; j2 < 4; j2++) {
            #pragma unroll
            for (int nt2 = 0; nt2 < 3; nt2++) {
                int vrow = j2*16 + ((g & 1) << 3) + L;
                int vcol = nt2*16 + ((g >> 1) << 3);
                unsigned r0, r1, r2, r3;
                ldsm_x4_t(r0, r1, r2, r3, cvta_s(&Vs[cur][vrow*56 + vcol]));
                mma16816(oacc[nt2*2],   P[j2][0], P[j2][1], P[j2][2], P[j2][3], r0, r1);
                mma16816(oacc[nt2*2+1], P[j2][0], P[j2][1], P[j2][2], P[j2][3], r2, r3);
            }
        }
        __syncthreads();
    }

    lr0 += __shfl_xor_sync(0xffffffffu, lr0, 1);
    lr0 += __shfl_xor_sync(0xffffffffu, lr0, 2);
    lr1 += __shfl_xor_sync(0xffffffffu, lr1, 1);
    lr1 += __shfl_xor_sync(0xffffffffu, lr1, 2);

    float inv0 = 1.f / lr0, inv1 = 1.f / lr1;
    int n_0 = q0 + w*16 + (lane >> 2);
    int n_1 = n_0 + 8;
    #pragma unroll
    for (int nt = 0; nt < 6; nt++) {
        int d = nt*8 + ((lane & 3) << 1);
        size_t i0 = ((size_t)(b*NTOK + n_0))*CDIM + hh*HD + d;
        size_t i1 = ((size_t)(b*NTOK + n_1))*CDIM + hh*HD + d;
        float x00 = x[i0],  x01 = x[i0+1], x10 = x[i1], x11 = x[i1+1];
        float y00 = oacc[nt][0]*inv0 + x00;
        float y01 = oacc[nt][1]*inv0 + x01;
        float y10 = oacc[nt][2]*inv1 + x10;
        float y11 = oacc[nt][3]*inv1 + x11;
        *(float2*)&g_Y[i0] = make_float2(y00 + x00, y01 + x01);
        *(float2*)&g_Y[i1] = make_float2(y10 + x10, y11 + x11);
        *(__half2*)&g_Yh[i0] = __floats2half2_rn(y00, y01);
        *(__half2*)&g_Yh[i1] = __floats2half2_rn(y10, y11);
    }
}

// ---------------------------------------------------------------------------
extern "C" void kernel_launch(void* const* d_in, const int* in_sizes, int n_in,
                              void* d_out, int out_size)
{
    const float* x  = (const float*)d_in[0];
    const float* wq = (const float*)d_in[1];
    const float* bq = (const float*)d_in[2];
    const float* wk = (const float*)d_in[3];
    const float* bk = (const float*)d_in[4];
    const float* wv = (const float*)d_in[5];
    const float* bv = (const float*)d_in[6];
    const float* wo = (const float*)d_in[7];
    const float* bo = (const float*)d_in[8];
    float* out = (float*)d_out;

    static int smem_set = 0;
    if (!smem_set) {
        cudaFuncSetAttribute(hgemm128_kernel,
                             cudaFuncAttributeMaxDynamicSharedMemorySize, G128_SMEM);
        cudaFuncSetAttribute(hgemm64_kernel,
                             cudaFuncAttributeMaxDynamicSharedMemorySize, G64_SMEM);
        smem_set = 1;
    }

    cvt_all<<<(NCVT + 255)/256, 256>>>(x, wq, wk, wv, wo);

    cudaLaunchAttribute pdl[1];
    pdl[0].id = cudaLaunchAttributeProgrammaticStreamSerialization;
    pdl[0].val.programmaticStreamSerializationAllowed = 1;

    {   // QKV (PDL after cvt)
        cudaLaunchConfig_t cfg = {};
        cfg.gridDim = dim3(CDIM/128, MROWS/128, 3);
        cfg.blockDim = dim3(256, 1, 1);
        cfg.dynamicSmemBytes = G128_SMEM;
        cfg.attrs = pdl; cfg.numAttrs = 1;
        cudaLaunchKernelEx(&cfg, hgemm128_kernel, bq, bk, bv);
    }
    {   // attention (PDL after QKV)
        cudaLaunchConfig_t cfg = {};
        cfg.gridDim = dim3(NTOK/128, BATCH*HEADS, 1);
        cfg.blockDim = dim3(256, 1, 1);
        cfg.dynamicSmemBytes = 0;
        cfg.attrs = pdl; cfg.numAttrs = 1;
        cudaLaunchKernelEx(&cfg, fattn_kernel, x);
    }
    {   // O-projection (PDL after attention)
        cudaLaunchConfig_t cfg = {};
        cfg.gridDim = dim3(CDIM/128, MROWS/64, 1);
        cfg.blockDim = dim3(256, 1, 1);
        cfg.dynamicSmemBytes = G64_SMEM;
        cfg.attrs = pdl; cfg.numAttrs = 1;
        cudaLaunchKernelEx(&cfg, hgemm64_kernel, bo, out);
    }
}

// round 16
// speedup vs baseline: 1.1620x; 1.0227x over previous
#include <cuda_runtime.h>
#include <cuda_fp16.h>
#include <cstdint>
#include <math.h>

#define BATCH   4
#define NTOK    2048
#define CDIM    768
#define HEADS   16
#define HD      48
#define MROWS   (BATCH*NTOK)          // 8192
#define SCALE   0.14433756729740643f  // 48^-0.5
#define LOG2E   1.4426950408889634f
#define QSC     (SCALE*LOG2E)

// ---------------- scratch (device globals; no allocation allowed) ----------
__device__ __align__(256) __half g_Xh[(size_t)MROWS*CDIM];
__device__ __align__(256) __half g_Wh[4][(size_t)CDIM*CDIM];   // q,k,v,o
__device__ __align__(256) __half g_Qh[(size_t)MROWS*CDIM];     // [B,H,N,D], Q pre-scaled by SCALE*log2e
__device__ __align__(256) __half g_Kh[(size_t)MROWS*CDIM];
__device__ __align__(256) __half g_Vh[(size_t)MROWS*CDIM];
__device__ __align__(256) __half g_Yx[(size_t)MROWS*CDIM];     // y + x (fp16 residual)
__device__ __align__(256) __half g_Yh[(size_t)MROWS*CDIM];     // fp16 y (GEMM input)

// ------------------------------ helpers ------------------------------------
__device__ __forceinline__ unsigned cvta_s(const void* p) {
    return (unsigned)__cvta_generic_to_shared(p);
}
__device__ __forceinline__ void ldsm_x4(unsigned& r0, unsigned& r1,
                                        unsigned& r2, unsigned& r3, unsigned a) {
    asm volatile("ldmatrix.sync.aligned.m8n8.x4.shared.b16 {%0,%1,%2,%3},[%4];"
                 : "=r"(r0), "=r"(r1), "=r"(r2), "=r"(r3) : "r"(a));
}
__device__ __forceinline__ void ldsm_x4_t(unsigned& r0, unsigned& r1,
                                          unsigned& r2, unsigned& r3, unsigned a) {
    asm volatile("ldmatrix.sync.aligned.m8n8.x4.trans.shared.b16 {%0,%1,%2,%3},[%4];"
                 : "=r"(r0), "=r"(r1), "=r"(r2), "=r"(r3) : "r"(a));
}
__device__ __forceinline__ void mma16816(float* c, unsigned a0, unsigned a1,
                                         unsigned a2, unsigned a3,
                                         unsigned b0, unsigned b1) {
    asm volatile("mma.sync.aligned.m16n8k16.row.col.f32.f16.f16.f32 "
                 "{%0,%1,%2,%3},{%4,%5,%6,%7},{%8,%9},{%0,%1,%2,%3};"
                 : "+f"(c[0]), "+f"(c[1]), "+f"(c[2]), "+f"(c[3])
                 : "r"(a0), "r"(a1), "r"(a2), "r"(a3), "r"(b0), "r"(b1));
}
__device__ __forceinline__ unsigned f2_to_h2(float a, float b) {
    __half2 h = __floats2half2_rn(a, b);
    return *reinterpret_cast<unsigned*>(&h);
}
__device__ __forceinline__ unsigned ex2h2(unsigned s) {
    unsigned d;
    asm("ex2.approx.f16x2 %0, %1;" : "=r"(d) : "r"(s));
    return d;
}
__device__ __forceinline__ unsigned hadd2u(unsigned a, unsigned b) {
    unsigned d;
    asm("add.f16x2 %0, %1, %2;" : "=r"(d) : "r"(a), "r"(b));
    return d;
}
__device__ __forceinline__ void cp_async16(unsigned saddr, const void* gaddr) {
    asm volatile("cp.async.cg.shared.global [%0], [%1], 16;"
                 :: "r"(saddr), "l"(gaddr) : "memory");
}
__device__ __forceinline__ void cp_commit() {
    asm volatile("cp.async.commit_group;" ::: "memory");
}
#define SW128(o) ((o) ^ (((o) >> 3) & 0x70))

// ---------------------------------------------------------------------------
// fused fp32 -> fp16 conversion (2 float4 per thread)
// ---------------------------------------------------------------------------
#define N4X (MROWS*CDIM/4)
#define N4W (CDIM*CDIM/4)
#define NCVT ((N4X + 4*N4W) / 2)

__global__ void cvt_all(const float* __restrict__ x,
                        const float* __restrict__ wq, const float* __restrict__ wk,
                        const float* __restrict__ wv, const float* __restrict__ wo)
{
    int t = blockIdx.x * 256 + threadIdx.x;
    if (t >= NCVT) return;
    #pragma unroll
    for (int rep = 0; rep < 2; rep++) {
        int i = t * 2 + rep;
        const float* src;
        __half2* dst;
        int off;
        if (i < N4X) {
            src = x; dst = (__half2*)g_Xh; off = i;
        } else {
            int j = i - N4X;
            int w = j / N4W;
            off = j - w * N4W;
            src = (w == 0) ? wq : (w == 1) ? wk : (w == 2) ? wv : wo;
            dst = (__half2*)g_Wh[w];
        }
        float4 v = ((const float4*)src)[off];
        dst[2*off]   = __floats2half2_rn(v.x, v.y);
        dst[2*off+1] = __floats2half2_rn(v.z, v.w);
    }
}

// ---------------------------------------------------------------------------
// HGEMM-128: 128x128 CTA tile, BK=64, 3-stage cp.async, SW128, (256,2).
// QKV: mode = blockIdx.z -> scatter to g_Qh/g_Kh/g_Vh fp16 (Q scaled QSC).
// ---------------------------------------------------------------------------
#define NIT   12              // 768 / 64
#define G128_STG 32768
#define G128_SMEM (3*G128_STG)

__global__ __launch_bounds__(256, 2) void hgemm128_kernel(
    const float* __restrict__ b0p, const float* __restrict__ b1p,
    const float* __restrict__ b2p)
{
    cudaGridDependencySynchronize();   // PDL: wait for cvt_all's writes

    extern __shared__ __align__(1024) char smraw[];
    unsigned smb = cvta_s(smraw);

    int tid = threadIdx.x, lane = tid & 31, warp = tid >> 5;
    int m0 = blockIdx.y * 128, n0 = blockIdx.x * 128;
    int mode = blockIdx.z;

    const __half* A = g_Xh;
    const __half* W = g_Wh[mode];
    const float* bias = (mode == 0) ? b0p : (mode == 1 ? b1p : b2p);

    int wm = (warp >> 2) * 64, wn = (warp & 3) * 32;
    int g = lane >> 3, L = lane & 7;

    float acc[4][4][4];
    #pragma unroll
    for (int i = 0; i < 4; i++)
        #pragma unroll
        for (int j = 0; j < 4; j++)
            #pragma unroll
            for (int e = 0; e < 4; e++) acc[i][j][e] = 0.f;

    auto load_tile = [&](int kt, int st) {
        #pragma unroll
        for (int p = 0; p < 4; p++) {
            int idx = tid + p * 256;            // 0..1023
            int row = idx >> 3, c16 = idx & 7;
            unsigned off = SW128((unsigned)(row * 128 + c16 * 16));
            cp_async16(smb + st * G128_STG + off,
                       A + (size_t)(m0 + row) * CDIM + kt * 64 + c16 * 8);
            cp_async16(smb + st * G128_STG + 16384 + off,
                       W + (size_t)(n0 + row) * CDIM + kt * 64 + c16 * 8);
        }
        cp_commit();
    };

    load_tile(0, 0);
    load_tile(1, 1);

    for (int c = 0; c < NIT; c++) {
        if (c < NIT - 1) asm volatile("cp.async.wait_group 1;" ::: "memory");
        else             asm volatile("cp.async.wait_group 0;" ::: "memory");
        __syncthreads();
        if (c + 2 < NIT) load_tile(c + 2, (c + 2) % 3);

        unsigned ab = smb + (c % 3) * G128_STG;
        unsigned bb = ab + 16384;

        #pragma unroll
        for (int s = 0; s < 4; s++) {
            int kbA = s * 32 + ((lane >> 4) << 4);
            unsigned af[4][4];
            #pragma unroll
            for (int mt = 0; mt < 4; mt++) {
                unsigned row = wm + mt * 16 + (lane & 15);
                ldsm_x4(af[mt][0], af[mt][1], af[mt][2], af[mt][3],
                        ab + SW128(row * 128 + kbA));
            }
            unsigned bf[4][2];
            int kbB = s * 32 + ((g & 1) << 4);
            #pragma unroll
            for (int nt2 = 0; nt2 < 2; nt2++) {
                unsigned brow = wn + nt2 * 16 + ((g >> 1) << 3) + L;
                unsigned r0, r1, r2, r3;
                ldsm_x4(r0, r1, r2, r3, bb + SW128(brow * 128 + kbB));
                bf[nt2*2][0] = r0;   bf[nt2*2][1] = r1;
                bf[nt2*2+1][0] = r2; bf[nt2*2+1][1] = r3;
            }
            #pragma unroll
            for (int mt = 0; mt < 4; mt++)
                #pragma unroll
                for (int nt = 0; nt < 4; nt++)
                    mma16816(acc[mt][nt], af[mt][0], af[mt][1], af[mt][2],
                             af[mt][3], bf[nt][0], bf[nt][1]);
        }
    }

    __half* dst = (mode == 0) ? g_Qh : ((mode == 1) ? g_Kh : g_Vh);
    float sc = (mode == 0) ? QSC : 1.f;
    #pragma unroll
    for (int mt = 0; mt < 4; mt++) {
        #pragma unroll
        for (int nt = 0; nt < 4; nt++) {
            int mr = m0 + wm + mt*16 + (lane >> 2);
            int c  = n0 + wn + nt*8 + ((lane & 3) << 1);
            int hh = c / HD, d = c - hh*HD;
            int bb2 = mr >> 11, nn = mr & 2047;
            size_t base = (size_t)(bb2*HEADS + hh) * NTOK * HD + d;
            __half2 v0 = __floats2half2_rn((acc[mt][nt][0] + bias[c])*sc,
                                           (acc[mt][nt][1] + bias[c+1])*sc);
            __half2 v1 = __floats2half2_rn((acc[mt][nt][2] + bias[c])*sc,
                                           (acc[mt][nt][3] + bias[c+1])*sc);
            *(__half2*)&dst[base + (size_t)nn*HD]     = v0;
            *(__half2*)&dst[base + (size_t)(nn+8)*HD] = v1;
        }
    }
}

// ---------------------------------------------------------------------------
// HGEMM-64: 64x128 CTA tile, BK=64, 3-stage cp.async, SW128, (256,3).
// O-projection: A=g_Yh, W=g_Wh[3]; out = acc + bias + g_Yx (fp16 residual).
// ---------------------------------------------------------------------------
#define G64_STG 24576
#define G64_SMEM (3*G64_STG)

__global__ __launch_bounds__(256, 3) void hgemm64_kernel(
    const float* __restrict__ bias, float* __restrict__ outp)
{
    cudaGridDependencySynchronize();   // PDL: wait for fattn's writes

    extern __shared__ __align__(1024) char smraw[];
    unsigned smb = cvta_s(smraw);

    int tid = threadIdx.x, lane = tid & 31, warp = tid >> 5;
    int m0 = blockIdx.y * 64, n0 = blockIdx.x * 128;

    const __half* A = g_Yh;
    const __half* W = g_Wh[3];

    int wm = (warp >> 2) * 32, wn = (warp & 3) * 32;
    int g = lane >> 3, L = lane & 7;

    float acc[2][4][4];
    #pragma unroll
    for (int i = 0; i < 2; i++)
        #pragma unroll
        for (int j = 0; j < 4; j++)
            #pragma unroll
            for (int e = 0; e < 4; e++) acc[i][j][e] = 0.f;

    auto load_tile = [&](int kt, int st) {
        #pragma unroll
        for (int p = 0; p < 6; p++) {
            int idx = tid + p * 256;            // 0..1535
            if (idx < 512) {
                int row = idx >> 3, c16 = idx & 7;
                unsigned off = SW128((unsigned)(row * 128 + c16 * 16));
                cp_async16(smb + st * G64_STG + off,
                           A + (size_t)(m0 + row) * CDIM + kt * 64 + c16 * 8);
            } else {
                int j = idx - 512;
                int row = j >> 3, c16 = j & 7;
                unsigned off = SW128((unsigned)(row * 128 + c16 * 16));
                cp_async16(smb + st * G64_STG + 8192 + off,
                           W + (size_t)(n0 + row) * CDIM + kt * 64 + c16 * 8);
            }
        }
        cp_commit();
    };

    load_tile(0, 0);
    load_tile(1, 1);

    for (int c = 0; c < NIT; c++) {
        if (c < NIT - 1) asm volatile("cp.async.wait_group 1;" ::: "memory");
        else             asm volatile("cp.async.wait_group 0;" ::: "memory");
        __syncthreads();
        if (c + 2 < NIT) load_tile(c + 2, (c + 2) % 3);

        unsigned ab = smb + (c % 3) * G64_STG;
        unsigned bb = ab + 8192;

        #pragma unroll
        for (int s = 0; s < 4; s++) {
            int kbA = s * 32 + ((lane >> 4) << 4);
            unsigned af[2][4];
            #pragma unroll
            for (int mt = 0; mt < 2; mt++) {
                unsigned row = wm + mt * 16 + (lane & 15);
                ldsm_x4(af[mt][0], af[mt][1], af[mt][2], af[mt][3],
                        ab + SW128(row * 128 + kbA));
            }
            unsigned bf[4][2];
            int kbB = s * 32 + ((g & 1) << 4);
            #pragma unroll
            for (int nt2 = 0; nt2 < 2; nt2++) {
                unsigned brow = wn + nt2 * 16 + ((g >> 1) << 3) + L;
                unsigned r0, r1, r2, r3;
                ldsm_x4(r0, r1, r2, r3, bb + SW128(brow * 128 + kbB));
                bf[nt2*2][0] = r0;   bf[nt2*2][1] = r1;
                bf[nt2*2+1][0] = r2; bf[nt2*2+1][1] = r3;
            }
            #pragma unroll
            for (int mt = 0; mt < 2; mt++)
                #pragma unroll
                for (int nt = 0; nt < 4; nt++)
                    mma16816(acc[mt][nt], af[mt][0], af[mt][1], af[mt][2],
                             af[mt][3], bf[nt][0], bf[nt][1]);
        }
    }

    #pragma unroll
    for (int mt = 0; mt < 2; mt++) {
        #pragma unroll
        for (int nt = 0; nt < 4; nt++) {
            int mr = m0 + wm + mt*16 + (lane >> 2);
            int c  = n0 + wn + nt*8 + ((lane & 3) << 1);
            size_t i0 = (size_t)mr * CDIM + c;
            size_t i1 = (size_t)(mr + 8) * CDIM + c;
            __half2 r0 = *(const __half2*)&g_Yx[i0];
            __half2 r1 = *(const __half2*)&g_Yx[i1];
            float2 f0 = __half22float2(r0);
            float2 f1 = __half22float2(r1);
            outp[i0]   = acc[mt][nt][0] + bias[c]   + f0.x;
            outp[i0+1] = acc[mt][nt][1] + bias[c+1] + f0.y;
            outp[i1]   = acc[mt][nt][2] + bias[c]   + f1.x;
            outp[i1+1] = acc[mt][nt][3] + bias[c+1] + f1.y;
        }
    }
}

// ---------------------------------------------------------------------------
// FlashAttention fp16, no online max, cp.async K/V double-buffer with a
// SINGLE __syncthreads per iteration (prefetch issued after the barrier).
// Q pre-scaled by SCALE*log2e; P = ex2(s). Block = 128 q-rows, 8 warps.
// Writes g_Yh = y (fp16 GEMM input) and g_Yx = y + x (fp16 residual).
// ---------------------------------------------------------------------------
__global__ __launch_bounds__(256) void fattn_kernel(const float* __restrict__ x)
{
    cudaGridDependencySynchronize();   // PDL: wait for QKV writes

    __shared__ __half Qs[128*56];
    __shared__ __half Ks[2][64*56];
    __shared__ __half Vs[2][64*56];

    int tid = threadIdx.x, lane = tid & 31, w = tid >> 5;
    int bh = blockIdx.y, q0 = blockIdx.x * 128;
    int b = bh >> 4, hh = bh & 15;

    const __half* Qg = g_Qh + (size_t)bh * NTOK * HD;
    const __half* Kg = g_Kh + (size_t)bh * NTOK * HD;
    const __half* Vg = g_Vh + (size_t)bh * NTOK * HD;

    auto load_kv = [&](int kt, int bufi) {
        int k0 = kt * 64;
        #pragma unroll
        for (int i = 0; i < 3; i++) {
            int idx = tid + i * 256;
            int isv = idx >= 384;
            int c = isv ? idx - 384 : idx;
            int r = c / 6, cc = c % 6;
            const __half* gp = (isv ? Vg : Kg) + (size_t)(k0 + r) * HD + cc * 8;
            unsigned sa = cvta_s(&(isv ? Vs : Ks)[bufi][r * 56 + cc * 8]);
            cp_async16(sa, gp);
        }
        cp_commit();
    };

    for (int idx = tid; idx < 128*6; idx += 256) {
        int r = idx / 6, c = idx % 6;
        *(uint4*)&Qs[r*56 + c*8] =
            *(const uint4*)(Qg + (size_t)(q0 + r)*HD + c*8);
    }
    load_kv(0, 0);
    __syncthreads();

    unsigned qa[3][4];
    #pragma unroll
    for (int ks = 0; ks < 3; ks++)
        ldsm_x4(qa[ks][0], qa[ks][1], qa[ks][2], qa[ks][3],
                cvta_s(&Qs[(w*16 + (lane & 15))*56 + ks*16 + ((lane >> 4) << 3)]));

    float lr0 = 0.f, lr1 = 0.f;
    float oacc[6][4];
    #pragma unroll
    for (int i = 0; i < 6; i++)
        #pragma unroll
        for (int e = 0; e < 4; e++) oacc[i][e] = 0.f;

    int g = lane >> 3, L = lane & 7;
    const int NT = NTOK / 64;

    for (int kt = 0; kt < NT; kt++) {
        int cur = kt & 1;
        asm volatile("cp.async.wait_group 0;" ::: "memory");
        __syncthreads();
        if (kt + 1 < NT) load_kv(kt + 1, cur ^ 1);

        float sacc[8][4];
        #pragma unroll
        for (int i = 0; i < 8; i++)
            #pragma unroll
            for (int e = 0; e < 4; e++) sacc[i][e] = 0.f;

        #pragma unroll
        for (int ks = 0; ks < 3; ks++) {
            #pragma unroll
            for (int nt2 = 0; nt2 < 4; nt2++) {
                int brow = nt2*16 + ((g >> 1) << 3) + L;
                int bcol = ks*16 + ((g & 1) << 3);
                unsigned r0, r1, r2, r3;
                ldsm_x4(r0, r1, r2, r3, cvta_s(&Ks[cur][brow*56 + bcol]));
                mma16816(sacc[nt2*2],   qa[ks][0], qa[ks][1], qa[ks][2], qa[ks][3], r0, r1);
                mma16816(sacc[nt2*2+1], qa[ks][0], qa[ks][1], qa[ks][2], qa[ks][3], r2, r3);
            }
        }

        unsigned P[4][4];
        #pragma unroll
        for (int j2 = 0; j2 < 4; j2++) {
            P[j2][0] = ex2h2(f2_to_h2(sacc[2*j2][0],   sacc[2*j2][1]));
            P[j2][1] = ex2h2(f2_to_h2(sacc[2*j2][2],   sacc[2*j2][3]));
            P[j2][2] = ex2h2(f2_to_h2(sacc[2*j2+1][0], sacc[2*j2+1][1]));
            P[j2][3] = ex2h2(f2_to_h2(sacc[2*j2+1][2], sacc[2*j2+1][3]));
        }

        {
            unsigned s0 = hadd2u(hadd2u(P[0][0], P[0][2]), hadd2u(P[1][0], P[1][2]));
            unsigned s1 = hadd2u(hadd2u(P[2][0], P[2][2]), hadd2u(P[3][0], P[3][2]));
            s0 = hadd2u(s0, s1);
            float2 f0 = __half22float2(*reinterpret_cast<__half2*>(&s0));
            lr0 += f0.x + f0.y;
            unsigned t0 = hadd2u(hadd2u(P[0][1], P[0][3]), hadd2u(P[1][1], P[1][3]));
            unsigned t1 = hadd2u(hadd2u(P[2][1], P[2][3]), hadd2u(P[3][1], P[3][3]));
            t0 = hadd2u(t0, t1);
            float2 f1 = __half22float2(*reinterpret_cast<__half2*>(&t0));
            lr1 += f1.x + f1.y;
        }

        #pragma unroll
        for (int j2 = 0; j2 < 4; j2++) {
            #pragma unroll
            for (int nt2 = 0; nt2 < 3; nt2++) {
                int vrow = j2*16 + ((g & 1) << 3) + L;
                int vcol = nt2*16 + ((g >> 1) << 3);
                unsigned r0, r1, r2, r3;
                ldsm_x4_t(r0, r1, r2, r3, cvta_s(&Vs[cur][vrow*56 + vcol]));
                mma16816(oacc[nt2*2],   P[j2][0], P[j2][1], P[j2][2], P[j2][3], r0, r1);
                mma16816(oacc[nt2*2+1], P[j2][0], P[j2][1], P[j2][2], P[j2][3], r2, r3);
            }
        }
    }

    lr0 += __shfl_xor_sync(0xffffffffu, lr0, 1);
    lr0 += __shfl_xor_sync(0xffffffffu, lr0, 2);
    lr1 += __shfl_xor_sync(0xffffffffu, lr1, 1);
    lr1 += __shfl_xor_sync(0xffffffffu, lr1, 2);

    float inv0 = 1.f / lr0, inv1 = 1.f / lr1;
    int n_0 = q0 + w*16 + (lane >> 2);
    int n_1 = n_0 + 8;
    #pragma unroll
    for (int nt = 0; nt < 6; nt++) {
        int d = nt*8 + ((lane & 3) << 1);
        size_t i0 = ((size_t)(b*NTOK + n_0))*CDIM + hh*HD + d;
        size_t i1 = ((size_t)(b*NTOK + n_1))*CDIM + hh*HD + d;
        float x00 = x[i0],  x01 = x[i0+1], x10 = x[i1], x11 = x[i1+1];
        float y00 = oacc[nt][0]*inv0 + x00;
        float y01 = oacc[nt][1]*inv0 + x01;
        float y10 = oacc[nt][2]*inv1 + x10;
        float y11 = oacc[nt][3]*inv1 + x11;
        *(__half2*)&g_Yx[i0] = __floats2half2_rn(y00 + x00, y01 + x01);
        *(__half2*)&g_Yx[i1] = __floats2half2_rn(y10 + x10, y11 + x11);
        *(__half2*)&g_Yh[i0] = __floats2half2_rn(y00, y01);
        *(__half2*)&g_Yh[i1] = __floats2half2_rn(y10, y11);
    }
}

// ---------------------------------------------------------------------------
extern "C" void kernel_launch(void* const* d_in, const int* in_sizes, int n_in,
                              void* d_out, int out_size)
{
    const float* x  = (const float*)d_in[0];
    const float* wq = (const float*)d_in[1];
    const float* bq = (const float*)d_in[2];
    const float* wk = (const float*)d_in[3];
    const float* bk = (const float*)d_in[4];
    const float* wv = (const float*)d_in[5];
    const float* bv = (const float*)d_in[6];
    const float* wo = (const float*)d_in[7];
    const float* bo = (const float*)d_in[8];
    float* out = (float*)d_out;

    static int smem_set = 0;
    if (!smem_set) {
        cudaFuncSetAttribute(hgemm128_kernel,
                             cudaFuncAttributeMaxDynamicSharedMemorySize, G128_SMEM);
        cudaFuncSetAttribute(hgemm64_kernel,
                             cudaFuncAttributeMaxDynamicSharedMemorySize, G64_SMEM);
        smem_set = 1;
    }

    cvt_all<<<(NCVT + 255)/256, 256>>>(x, wq, wk, wv, wo);

    cudaLaunchAttribute pdl[1];
    pdl[0].id = cudaLaunchAttributeProgrammaticStreamSerialization;
    pdl[0].val.programmaticStreamSerializationAllowed = 1;

    {   // QKV (PDL after cvt)
        cudaLaunchConfig_t cfg = {};
        cfg.gridDim = dim3(CDIM/128, MROWS/128, 3);
        cfg.blockDim = dim3(256, 1, 1);
        cfg.dynamicSmemBytes = G128_SMEM;
        cfg.attrs = pdl; cfg.numAttrs = 1;
        cudaLaunchKernelEx(&cfg, hgemm128_kernel, bq, bk, bv);
    }
    {   // attention (PDL after QKV)
        cudaLaunchConfig_t cfg = {};
        cfg.gridDim = dim3(NTOK/128, BATCH*HEADS, 1);
        cfg.blockDim = dim3(256, 1, 1);
        cfg.dynamicSmemBytes = 0;
        cfg.attrs = pdl; cfg.numAttrs = 1;
        cudaLaunchKernelEx(&cfg, fattn_kernel, x);
    }
    {   // O-projection (PDL after attention)
        cudaLaunchConfig_t cfg = {};
        cfg.gridDim = dim3(CDIM/128, MROWS/64, 1);
        cfg.blockDim = dim3(256, 1, 1);
        cfg.dynamicSmemBytes = G64_SMEM;
        cfg.attrs = pdl; cfg.numAttrs = 1;
        cudaLaunchKernelEx(&cfg, hgemm64_kernel, bo, out);
    }
}